// round 1
// baseline (speedup 1.0000x reference)
#include <cuda_runtime.h>
#include <math.h>

#define FEAT    128
#define NRBF    20
#define NATOMS  8192
#define NEDGES  262144
#define NGRAPHS 128
#define SP      132   // padded shared stride for 128-wide tiles

// ---------------- device scratch (static allocation: allowed) ----------------
__device__ float g_phi[NATOMS * 384];   // phi = silu(s@W1+b1)@W2+b2
__device__ int   g_cnt[NATOMS];
__device__ int   g_off[NATOMS];
__device__ int   g_pos[NEDGES];
__device__ int   g_eid[NEDGES];

// ---------------- CSR build ----------------
__global__ void k_zero() {
    int i = blockIdx.x * 256 + threadIdx.x;
    if (i < NATOMS) g_cnt[i] = 0;
}

__global__ void k_hist(const int* __restrict__ nbrs) {
    int e = blockIdx.x * 256 + threadIdx.x;   // grid exactly covers NEDGES
    int src = nbrs[2 * e];
    g_pos[e] = atomicAdd(&g_cnt[src], 1);
}

__global__ void k_scan() {
    __shared__ int sh[1024];
    int t = threadIdx.x;
    int c[8];
    int run = 0;
#pragma unroll
    for (int j = 0; j < 8; j++) { int v = g_cnt[t * 8 + j]; c[j] = run; run += v; }
    sh[t] = run;
    __syncthreads();
    for (int ofs = 1; ofs < 1024; ofs <<= 1) {
        int v = (t >= ofs) ? sh[t - ofs] : 0;
        __syncthreads();
        sh[t] += v;
        __syncthreads();
    }
    int excl = sh[t] - run;   // exclusive prefix of this thread's chunk
#pragma unroll
    for (int j = 0; j < 8; j++) g_off[t * 8 + j] = excl + c[j];
}

__global__ void k_scatter(const int* __restrict__ nbrs) {
    int e = blockIdx.x * 256 + threadIdx.x;
    int src = nbrs[2 * e];
    g_eid[g_off[src] + g_pos[e]] = e;
}

// ---------------- fused phi-MLP + QKV + attention (one block per graph) ------
// shared layout (floats):
//  [0      .. 8448)   sS   : s tile, 64 x SP
//  [8448   .. 16896)  sH   : h (silu), later V, 64 x SP
//  [16896  .. 25344)  sQ   : Q, 64 x SP
//  [25344  .. 34048)  sKT  : K transposed, 128 x 68
//  [34048  .. 38400)  sST  : B staging 32 x SP / softmax P 64 x 68
#define OFF_S  0
#define OFF_H  8448
#define OFF_Q  16896
#define OFF_KT 25344
#define OFF_ST 34048
#define SMEM_FLOATS 38400

__device__ __forceinline__ void gemm_body(
    const float* sA, const float* __restrict__ Bg,
    int ldb, int cbase, float* sST,
    float acc[4][8], int tx, int ty, int tid)
{
#pragma unroll
    for (int r = 0; r < 4; r++)
#pragma unroll
        for (int j = 0; j < 8; j++) acc[r][j] = 0.f;

    for (int k0 = 0; k0 < 128; k0 += 32) {
        __syncthreads();   // protect stage vs previous readers
#pragma unroll
        for (int i = 0; i < 16; i++) {
            int idx = tid + i * 256;
            int kk = idx >> 7, cc = idx & 127;
            sST[kk * SP + cc] = Bg[(k0 + kk) * ldb + cbase + cc];
        }
        __syncthreads();
#pragma unroll 8
        for (int kk = 0; kk < 32; kk++) {
            float a0 = sA[(ty * 4 + 0) * SP + k0 + kk];
            float a1 = sA[(ty * 4 + 1) * SP + k0 + kk];
            float a2 = sA[(ty * 4 + 2) * SP + k0 + kk];
            float a3 = sA[(ty * 4 + 3) * SP + k0 + kk];
            const float4 b0 = *(const float4*)&sST[kk * SP + tx * 8];
            const float4 b1 = *(const float4*)&sST[kk * SP + tx * 8 + 4];
            float bb[8] = {b0.x, b0.y, b0.z, b0.w, b1.x, b1.y, b1.z, b1.w};
#pragma unroll
            for (int j = 0; j < 8; j++) {
                acc[0][j] = fmaf(a0, bb[j], acc[0][j]);
                acc[1][j] = fmaf(a1, bb[j], acc[1][j]);
                acc[2][j] = fmaf(a2, bb[j], acc[2][j]);
                acc[3][j] = fmaf(a3, bb[j], acc[3][j]);
            }
        }
    }
}

__global__ void __launch_bounds__(256)
k_phi_attn(const float* __restrict__ s_in,
           const float* __restrict__ W1, const float* __restrict__ b1,
           const float* __restrict__ W2, const float* __restrict__ b2,
           const float* __restrict__ Wd, const float* __restrict__ bd,
           float* __restrict__ out_s)
{
    extern __shared__ float sm[];
    const int g = blockIdx.x, tid = threadIdx.x;
    const int tx = tid & 15, ty = tid >> 4;
    float* sS  = sm + OFF_S;
    float* sH  = sm + OFF_H;
    float* sQ  = sm + OFF_Q;
    float* sKT = sm + OFF_KT;
    float* sST = sm + OFF_ST;

    // load s rows for this graph
    const float* sg = s_in + (size_t)g * 64 * FEAT;
    for (int i = tid; i < 64 * FEAT; i += 256) {
        int r = i >> 7, cc = i & 127;
        sS[r * SP + cc] = sg[i];
    }

    float acc[4][8];

    // phase 1: h = silu(s @ W1 + b1)
    gemm_body(sS, W1, 128, 0, sST, acc, tx, ty, tid);
#pragma unroll
    for (int r = 0; r < 4; r++)
#pragma unroll
        for (int j = 0; j < 8; j++) {
            float x = acc[r][j] + b1[tx * 8 + j];
            float h = __fdividef(x, 1.f + __expf(-x));
            sH[(ty * 4 + r) * SP + tx * 8 + j] = h;
        }

    // phase 2: phi = h @ W2 + b2 -> global
#pragma unroll
    for (int ci = 0; ci < 3; ci++) {
        int cb = ci * 128;
        gemm_body(sH, W2, 384, cb, sST, acc, tx, ty, tid);
#pragma unroll
        for (int r = 0; r < 4; r++) {
            int row = g * 64 + ty * 4 + r;
            float4 o0, o1;
            o0.x = acc[r][0] + b2[cb + tx * 8 + 0];
            o0.y = acc[r][1] + b2[cb + tx * 8 + 1];
            o0.z = acc[r][2] + b2[cb + tx * 8 + 2];
            o0.w = acc[r][3] + b2[cb + tx * 8 + 3];
            o1.x = acc[r][4] + b2[cb + tx * 8 + 4];
            o1.y = acc[r][5] + b2[cb + tx * 8 + 5];
            o1.z = acc[r][6] + b2[cb + tx * 8 + 6];
            o1.w = acc[r][7] + b2[cb + tx * 8 + 7];
            *(float4*)&g_phi[(size_t)row * 384 + cb + tx * 8]     = o0;
            *(float4*)&g_phi[(size_t)row * 384 + cb + tx * 8 + 4] = o1;
        }
    }

    // phase 3: qkv = s @ Wd + bd ; Q -> sQ, K -> sKT (transposed), V -> sH
    gemm_body(sS, Wd, 384, 0, sST, acc, tx, ty, tid);
#pragma unroll
    for (int r = 0; r < 4; r++)
#pragma unroll
        for (int j = 0; j < 8; j++)
            sQ[(ty * 4 + r) * SP + tx * 8 + j] = acc[r][j] + bd[tx * 8 + j];

    gemm_body(sS, Wd, 384, 128, sST, acc, tx, ty, tid);
#pragma unroll
    for (int r = 0; r < 4; r++)
#pragma unroll
        for (int j = 0; j < 8; j++)
            sKT[(tx * 8 + j) * 68 + (ty * 4 + r)] = acc[r][j] + bd[128 + tx * 8 + j];

    gemm_body(sS, Wd, 384, 256, sST, acc, tx, ty, tid);
#pragma unroll
    for (int r = 0; r < 4; r++)
#pragma unroll
        for (int j = 0; j < 8; j++)
            sH[(ty * 4 + r) * SP + tx * 8 + j] = acc[r][j] + bd[256 + tx * 8 + j];

    __syncthreads();

    // phase 4a: scores = Q @ K^T / sqrt(FEAT)  (64x64, 4x4 tiles) -> sST (stride 68)
    {
        float sa[4][4];
#pragma unroll
        for (int r = 0; r < 4; r++)
#pragma unroll
            for (int j = 0; j < 4; j++) sa[r][j] = 0.f;
#pragma unroll 8
        for (int kk = 0; kk < 128; kk++) {
            float a0 = sQ[(ty * 4 + 0) * SP + kk];
            float a1 = sQ[(ty * 4 + 1) * SP + kk];
            float a2 = sQ[(ty * 4 + 2) * SP + kk];
            float a3 = sQ[(ty * 4 + 3) * SP + kk];
            const float4 b = *(const float4*)&sKT[kk * 68 + tx * 4];
            float bb[4] = {b.x, b.y, b.z, b.w};
#pragma unroll
            for (int j = 0; j < 4; j++) {
                sa[0][j] = fmaf(a0, bb[j], sa[0][j]);
                sa[1][j] = fmaf(a1, bb[j], sa[1][j]);
                sa[2][j] = fmaf(a2, bb[j], sa[2][j]);
                sa[3][j] = fmaf(a3, bb[j], sa[3][j]);
            }
        }
        const float scale = 0.08838834764831845f; // 1/sqrt(128)
        __syncthreads();  // stage no longer used; safe to write P
#pragma unroll
        for (int r = 0; r < 4; r++)
#pragma unroll
            for (int j = 0; j < 4; j++)
                sST[(ty * 4 + r) * 68 + tx * 4 + j] = sa[r][j] * scale;
    }
    __syncthreads();

    // softmax over rows (64 rows, one thread each)
    if (tid < 64) {
        float* row = sST + tid * 68;
        float mx = row[0];
        for (int j = 1; j < 64; j++) mx = fmaxf(mx, row[j]);
        float sum = 0.f;
        for (int j = 0; j < 64; j++) { float e = __expf(row[j] - mx); row[j] = e; sum += e; }
        float inv = __fdividef(1.f, sum);
        for (int j = 0; j < 64; j++) row[j] *= inv;
    }
    __syncthreads();

    // phase 4b: att = P @ V  -> out_s (delta_s init; edge kernel adds to it)
    {
        float aa[4][8];
#pragma unroll
        for (int r = 0; r < 4; r++)
#pragma unroll
            for (int j = 0; j < 8; j++) aa[r][j] = 0.f;
#pragma unroll 8
        for (int kk = 0; kk < 64; kk++) {
            float a0 = sST[(ty * 4 + 0) * 68 + kk];
            float a1 = sST[(ty * 4 + 1) * 68 + kk];
            float a2 = sST[(ty * 4 + 2) * 68 + kk];
            float a3 = sST[(ty * 4 + 3) * 68 + kk];
            const float4 b0 = *(const float4*)&sH[kk * SP + tx * 8];
            const float4 b1 = *(const float4*)&sH[kk * SP + tx * 8 + 4];
            float bb[8] = {b0.x, b0.y, b0.z, b0.w, b1.x, b1.y, b1.z, b1.w};
#pragma unroll
            for (int j = 0; j < 8; j++) {
                aa[0][j] = fmaf(a0, bb[j], aa[0][j]);
                aa[1][j] = fmaf(a1, bb[j], aa[1][j]);
                aa[2][j] = fmaf(a2, bb[j], aa[2][j]);
                aa[3][j] = fmaf(a3, bb[j], aa[3][j]);
            }
        }
#pragma unroll
        for (int r = 0; r < 4; r++) {
            int row = g * 64 + ty * 4 + r;
            float4 o0 = {aa[r][0], aa[r][1], aa[r][2], aa[r][3]};
            float4 o1 = {aa[r][4], aa[r][5], aa[r][6], aa[r][7]};
            *(float4*)&out_s[(size_t)row * FEAT + tx * 8]     = o0;
            *(float4*)&out_s[(size_t)row * FEAT + tx * 8 + 4] = o1;
        }
    }
}

// ---------------- edge message pass, one block per destination atom ----------
__global__ void __launch_bounds__(128, 4)
k_edge(const float* __restrict__ v_j, const float* __restrict__ r_ij,
       const int* __restrict__ nbrs,
       const float* __restrict__ Wr, const float* __restrict__ br,
       float* __restrict__ out)
{
    const int i = blockIdx.x;        // segment (src atom)
    const int c = threadIdx.x;       // feature 0..127

    // Wr columns for this thread's 3 feature slots, kept in registers
    float wr0[NRBF], wr1[NRBF], wr2[NRBF];
#pragma unroll
    for (int n = 0; n < NRBF; n++) {
        wr0[n] = __ldg(&Wr[n * 384 + c]);
        wr1[n] = __ldg(&Wr[n * 384 + 128 + c]);
        wr2[n] = __ldg(&Wr[n * 384 + 256 + c]);
    }
    const float br0 = __ldg(&br[c]);
    const float br1 = __ldg(&br[128 + c]);
    const float br2 = __ldg(&br[256 + c]);

    __shared__ float srx[32], sry[32], srz[32];
    __shared__ int   sdst[32];

    const int deg = g_cnt[i];
    const int start = g_off[i];

    float accs = 0.f, avx = 0.f, avy = 0.f, avz = 0.f;

    for (int base = 0; base < deg; base += 32) {
        int m = min(32, deg - base);
        __syncthreads();
        if (c < m) {
            int e = g_eid[start + base + c];
            sdst[c] = nbrs[2 * e + 1];
            const float* rp = r_ij + 3 * (size_t)e;
            srx[c] = rp[0]; sry[c] = rp[1]; srz[c] = rp[2];
        }
        __syncthreads();
        for (int j = 0; j < m; j++) {
            float rx = srx[j], ry = sry[j], rz = srz[j];
            float d2 = fmaf(rx, rx, fmaf(ry, ry, rz * rz));
            float d  = sqrtf(d2);
            if (d >= 5.0f) continue;                 // env == 0 exactly
            float invd = __fdividef(1.0f, d);
            float x = 0.6283185307179586f * d;       // pi*d/5 (< pi here)
            float s1, c1;
            __sincosf(x, &s1, &c1);
            float c2  = 2.0f * c1;
            float env = fmaf(0.5f, c1, 0.5f);
            // sin(n x) via Chebyshev recurrence, fused with Wr dot
            float sp = 0.f, sc_ = s1;
            float w0 = s1 * wr0[0], w1 = s1 * wr1[0], w2 = s1 * wr2[0];
#pragma unroll
            for (int n = 1; n < NRBF; n++) {
                float sn = fmaf(c2, sc_, -sp);
                sp = sc_; sc_ = sn;
                w0 = fmaf(sn, wr0[n], w0);
                w1 = fmaf(sn, wr1[n], w1);
                w2 = fmaf(sn, wr2[n], w2);
            }
            float einv = env * invd;
            float ws0 = fmaf(w0, einv, br0 * env);
            float ws1 = fmaf(w1, einv, br1 * env);
            float ws2 = fmaf(w2, einv, br2 * env);

            int dst = sdst[j];
            const float* ph = g_phi + (size_t)dst * 384;
            float a0 = ph[c]       * ws0;
            float a1 = ph[c + 128] * ws1;
            float a2 = ph[c + 256] * ws2;
            accs += a1;

            const float* vv = v_j + ((size_t)dst * 128 + c) * 3;
            float ux = rx * invd, uy = ry * invd, uz = rz * invd;
            avx = fmaf(a2, ux, fmaf(a0, vv[0], avx));
            avy = fmaf(a2, uy, fmaf(a0, vv[1], avy));
            avz = fmaf(a2, uz, fmaf(a0, vv[2], avz));
        }
    }

    // outputs: [delta_s (8192x128) | delta_v (8192x128x3)]
    size_t idx = (size_t)i * FEAT + c;
    float* outs = out;
    float* outv = out + (size_t)NATOMS * FEAT;
    outs[idx] = outs[idx] + accs;                  // add to attention result
    outv[idx * 3 + 0] = avx;
    outv[idx * 3 + 1] = avy;
    outv[idx * 3 + 2] = avz;
}

// ---------------- launch ----------------
extern "C" void kernel_launch(void* const* d_in, const int* in_sizes, int n_in,
                              void* d_out, int out_size)
{
    const float* s_j  = (const float*)d_in[0];
    const float* v_j  = (const float*)d_in[1];
    const float* r_ij = (const float*)d_in[2];
    const int*   nbrs = (const int*)  d_in[3];
    // d_in[4] = num_atoms (unused: all graphs full)
    const float* W1 = (const float*)d_in[5];
    const float* b1 = (const float*)d_in[6];
    const float* W2 = (const float*)d_in[7];
    const float* b2 = (const float*)d_in[8];
    const float* Wr = (const float*)d_in[9];
    const float* br = (const float*)d_in[10];
    const float* Wd = (const float*)d_in[11];
    const float* bd = (const float*)d_in[12];
    float* out = (float*)d_out;

    cudaFuncSetAttribute(k_phi_attn, cudaFuncAttributeMaxDynamicSharedMemorySize,
                         SMEM_FLOATS * sizeof(float));

    k_zero<<<32, 256>>>();
    k_hist<<<NEDGES / 256, 256>>>(nbrs);
    k_scan<<<1, 1024>>>();
    k_scatter<<<NEDGES / 256, 256>>>(nbrs);
    k_phi_attn<<<NGRAPHS, 256, SMEM_FLOATS * sizeof(float)>>>(
        s_j, W1, b1, W2, b2, Wd, bd, out);
    k_edge<<<NATOMS, 128>>>(v_j, r_ij, nbrs, Wr, br, out);
}

// round 2
// speedup vs baseline: 1.2879x; 1.2879x over previous
#include <cuda_runtime.h>
#include <math.h>

#define FEAT    128
#define NRBF    20
#define NATOMS  8192
#define NEDGES  262144
#define NGRAPHS 128
#define APB     8

typedef unsigned long long ull;

// ---------------- f32x2 packed helpers ----------------
__device__ __forceinline__ ull f2pack(float lo, float hi) {
    ull r; asm("mov.b64 %0,{%1,%2};" : "=l"(r) : "f"(lo), "f"(hi)); return r;
}
__device__ __forceinline__ void f2unpack(ull p, float& a, float& b) {
    asm("mov.b64 {%0,%1},%2;" : "=f"(a), "=f"(b) : "l"(p));
}
__device__ __forceinline__ ull f2fma(ull a, ull b, ull c) {
    ull d; asm("fma.rn.f32x2 %0,%1,%2,%3;" : "=l"(d) : "l"(a), "l"(b), "l"(c)); return d;
}
__device__ __forceinline__ ull f2mul(ull a, ull b) {
    ull d; asm("mul.rn.f32x2 %0,%1,%2;" : "=l"(d) : "l"(a), "l"(b)); return d;
}

// ---------------- device scratch ----------------
__device__ float g_phi[NATOMS * 384];
__device__ float g_qkv[NATOMS * 384];
__device__ float g_h  [NATOMS * 128];
__device__ float g_vt [NATOMS * 384];
__device__ int   g_cnt[NATOMS];
__device__ int   g_off[NATOMS];
__device__ int   g_pos[NEDGES];
__device__ int   g_eid[NEDGES];

// ---------------- CSR build ----------------
__global__ void k_zero() {
    int i = blockIdx.x * 256 + threadIdx.x;
    if (i < NATOMS) g_cnt[i] = 0;
}
__global__ void k_hist(const int* __restrict__ nbrs) {
    int e = blockIdx.x * 256 + threadIdx.x;
    int src = nbrs[2 * e];
    g_pos[e] = atomicAdd(&g_cnt[src], 1);
}
__global__ void k_scan() {
    __shared__ int sh[1024];
    int t = threadIdx.x;
    int c[8];
    int run = 0;
#pragma unroll
    for (int j = 0; j < 8; j++) { int v = g_cnt[t * 8 + j]; c[j] = run; run += v; }
    sh[t] = run;
    __syncthreads();
    for (int ofs = 1; ofs < 1024; ofs <<= 1) {
        int v = (t >= ofs) ? sh[t - ofs] : 0;
        __syncthreads();
        sh[t] += v;
        __syncthreads();
    }
    int excl = sh[t] - run;
#pragma unroll
    for (int j = 0; j < 8; j++) g_off[t * 8 + j] = excl + c[j];
}
__global__ void k_scatter(const int* __restrict__ nbrs) {
    int e = blockIdx.x * 256 + threadIdx.x;
    int src = nbrs[2 * e];
    g_eid[g_off[src] + g_pos[e]] = e;
}

// ---------------- v transpose: (atom, feat, 3) -> (atom, 3, feat) ----------------
__global__ void k_vt(const float* __restrict__ v) {
    int i = blockIdx.x, c = threadIdx.x;
    const float* p = v + ((size_t)i * FEAT + c) * 3;
    float x = p[0], y = p[1], z = p[2];
    g_vt[(size_t)i * 384 + c]       = x;
    g_vt[(size_t)i * 384 + 128 + c] = y;
    g_vt[(size_t)i * 384 + 256 + c] = z;
}

// ---------------- tiled SGEMM: C[8192 x N] = A[8192 x K] @ B[K x N] + bias ----
__global__ void __launch_bounds__(256)
k_gemm(const float* __restrict__ A, const float* __restrict__ B,
       const float* __restrict__ bias, float* __restrict__ C,
       int K, int N, int act)
{
    __shared__ __align__(16) float As[16][68];
    __shared__ __align__(16) float Bs[16][68];
    const int tid = threadIdx.x;
    const int tx = tid & 15, ty = tid >> 4;
    const int bx = blockIdx.x * 64, by = blockIdx.y * 64;
    const int ar = tid >> 2, aq = tid & 3;      // A loader: row, k-quad
    const int bk = tid >> 4, bc = (tid & 15) * 4; // B loader: k, col

    ull acc[4][2];
#pragma unroll
    for (int r = 0; r < 4; r++) { acc[r][0] = 0ull; acc[r][1] = 0ull; }

    for (int k0 = 0; k0 < K; k0 += 16) {
        __syncthreads();
        float4 av = *(const float4*)&A[(size_t)(by + ar) * K + k0 + aq * 4];
        As[aq * 4 + 0][ar] = av.x; As[aq * 4 + 1][ar] = av.y;
        As[aq * 4 + 2][ar] = av.z; As[aq * 4 + 3][ar] = av.w;
        *(float4*)&Bs[bk][bc] = *(const float4*)&B[(size_t)(k0 + bk) * N + bx + bc];
        __syncthreads();
#pragma unroll
        for (int kk = 0; kk < 16; kk++) {
            float4 a4 = *(const float4*)&As[kk][ty * 4];
            ull b0 = *(const ull*)&Bs[kk][tx * 4];
            ull b1 = *(const ull*)&Bs[kk][tx * 4 + 2];
            ull s;
            s = f2pack(a4.x, a4.x); acc[0][0] = f2fma(s, b0, acc[0][0]); acc[0][1] = f2fma(s, b1, acc[0][1]);
            s = f2pack(a4.y, a4.y); acc[1][0] = f2fma(s, b0, acc[1][0]); acc[1][1] = f2fma(s, b1, acc[1][1]);
            s = f2pack(a4.z, a4.z); acc[2][0] = f2fma(s, b0, acc[2][0]); acc[2][1] = f2fma(s, b1, acc[2][1]);
            s = f2pack(a4.w, a4.w); acc[3][0] = f2fma(s, b0, acc[3][0]); acc[3][1] = f2fma(s, b1, acc[3][1]);
        }
    }
    float b0 = bias[bx + tx * 4], b1 = bias[bx + tx * 4 + 1];
    float b2 = bias[bx + tx * 4 + 2], b3 = bias[bx + tx * 4 + 3];
#pragma unroll
    for (int r = 0; r < 4; r++) {
        float o0, o1, o2, o3;
        f2unpack(acc[r][0], o0, o1);
        f2unpack(acc[r][1], o2, o3);
        o0 += b0; o1 += b1; o2 += b2; o3 += b3;
        if (act) {
            o0 = __fdividef(o0, 1.f + __expf(-o0));
            o1 = __fdividef(o1, 1.f + __expf(-o1));
            o2 = __fdividef(o2, 1.f + __expf(-o2));
            o3 = __fdividef(o3, 1.f + __expf(-o3));
        }
        *(float4*)&C[(size_t)(by + ty * 4 + r) * N + bx + tx * 4] = make_float4(o0, o1, o2, o3);
    }
}

// ---------------- per-graph attention ----------------
// smem: Q 64x132 | KT 128x68 | V 64x132 | P 64x68
#define AT_SMEM 29952
__global__ void __launch_bounds__(256)
k_attn(const float* __restrict__ qkv, float* __restrict__ out_s)
{
    extern __shared__ float sm[];
    float* sQ  = sm;
    float* sKT = sm + 8448;
    float* sV  = sm + 17152;
    float* sP  = sm + 25600;
    const int g = blockIdx.x, tid = threadIdx.x;
    const int tx = tid & 15, ty = tid >> 4;

    const float* src = qkv + (size_t)g * 64 * 384;
    for (int idx = tid; idx < 64 * 384; idx += 256) {
        int r = idx / 384, col = idx - r * 384;
        float v = src[idx];
        if (col < 128)      sQ[r * 132 + col] = v;
        else if (col < 256) sKT[(col - 128) * 68 + r] = v;
        else                sV[r * 132 + (col - 256)] = v;
    }
    __syncthreads();

    // scores = Q @ K^T * scale
    {
        ull sa[4][2];
#pragma unroll
        for (int r = 0; r < 4; r++) { sa[r][0] = 0ull; sa[r][1] = 0ull; }
#pragma unroll 4
        for (int kk = 0; kk < 128; kk++) {
            ull b0 = *(const ull*)&sKT[kk * 68 + tx * 4];
            ull b1 = *(const ull*)&sKT[kk * 68 + tx * 4 + 2];
            float a0 = sQ[(ty * 4 + 0) * 132 + kk];
            float a1 = sQ[(ty * 4 + 1) * 132 + kk];
            float a2 = sQ[(ty * 4 + 2) * 132 + kk];
            float a3 = sQ[(ty * 4 + 3) * 132 + kk];
            ull s;
            s = f2pack(a0, a0); sa[0][0] = f2fma(s, b0, sa[0][0]); sa[0][1] = f2fma(s, b1, sa[0][1]);
            s = f2pack(a1, a1); sa[1][0] = f2fma(s, b0, sa[1][0]); sa[1][1] = f2fma(s, b1, sa[1][1]);
            s = f2pack(a2, a2); sa[2][0] = f2fma(s, b0, sa[2][0]); sa[2][1] = f2fma(s, b1, sa[2][1]);
            s = f2pack(a3, a3); sa[3][0] = f2fma(s, b0, sa[3][0]); sa[3][1] = f2fma(s, b1, sa[3][1]);
        }
        const float scale = 0.08838834764831845f;
#pragma unroll
        for (int r = 0; r < 4; r++) {
            float o0, o1, o2, o3;
            f2unpack(sa[r][0], o0, o1);
            f2unpack(sa[r][1], o2, o3);
            sP[(ty * 4 + r) * 68 + tx * 4 + 0] = o0 * scale;
            sP[(ty * 4 + r) * 68 + tx * 4 + 1] = o1 * scale;
            sP[(ty * 4 + r) * 68 + tx * 4 + 2] = o2 * scale;
            sP[(ty * 4 + r) * 68 + tx * 4 + 3] = o3 * scale;
        }
    }
    __syncthreads();

    if (tid < 64) {
        float* row = sP + tid * 68;
        float mx = row[0];
        for (int j = 1; j < 64; j++) mx = fmaxf(mx, row[j]);
        float sum = 0.f;
        for (int j = 0; j < 64; j++) { float e = __expf(row[j] - mx); row[j] = e; sum += e; }
        float inv = __fdividef(1.f, sum);
        for (int j = 0; j < 64; j++) row[j] *= inv;
    }
    __syncthreads();

    // att = P @ V
    {
        ull aa[4][4];
#pragma unroll
        for (int r = 0; r < 4; r++)
#pragma unroll
            for (int p = 0; p < 4; p++) aa[r][p] = 0ull;
#pragma unroll 4
        for (int kk = 0; kk < 64; kk++) {
            ull b0 = *(const ull*)&sV[kk * 132 + tx * 8];
            ull b1 = *(const ull*)&sV[kk * 132 + tx * 8 + 2];
            ull b2 = *(const ull*)&sV[kk * 132 + tx * 8 + 4];
            ull b3 = *(const ull*)&sV[kk * 132 + tx * 8 + 6];
            float a0 = sP[(ty * 4 + 0) * 68 + kk];
            float a1 = sP[(ty * 4 + 1) * 68 + kk];
            float a2 = sP[(ty * 4 + 2) * 68 + kk];
            float a3 = sP[(ty * 4 + 3) * 68 + kk];
            ull s;
            s = f2pack(a0, a0); aa[0][0]=f2fma(s,b0,aa[0][0]); aa[0][1]=f2fma(s,b1,aa[0][1]); aa[0][2]=f2fma(s,b2,aa[0][2]); aa[0][3]=f2fma(s,b3,aa[0][3]);
            s = f2pack(a1, a1); aa[1][0]=f2fma(s,b0,aa[1][0]); aa[1][1]=f2fma(s,b1,aa[1][1]); aa[1][2]=f2fma(s,b2,aa[1][2]); aa[1][3]=f2fma(s,b3,aa[1][3]);
            s = f2pack(a2, a2); aa[2][0]=f2fma(s,b0,aa[2][0]); aa[2][1]=f2fma(s,b1,aa[2][1]); aa[2][2]=f2fma(s,b2,aa[2][2]); aa[2][3]=f2fma(s,b3,aa[2][3]);
            s = f2pack(a3, a3); aa[3][0]=f2fma(s,b0,aa[3][0]); aa[3][1]=f2fma(s,b1,aa[3][1]); aa[3][2]=f2fma(s,b2,aa[3][2]); aa[3][3]=f2fma(s,b3,aa[3][3]);
        }
#pragma unroll
        for (int r = 0; r < 4; r++) {
            int row = g * 64 + ty * 4 + r;
            float o[8];
            f2unpack(aa[r][0], o[0], o[1]);
            f2unpack(aa[r][1], o[2], o[3]);
            f2unpack(aa[r][2], o[4], o[5]);
            f2unpack(aa[r][3], o[6], o[7]);
            *(float4*)&out_s[(size_t)row * FEAT + tx * 8]     = make_float4(o[0], o[1], o[2], o[3]);
            *(float4*)&out_s[(size_t)row * FEAT + tx * 8 + 4] = make_float4(o[4], o[5], o[6], o[7]);
        }
    }
}

// ---------------- edge message pass ----------------
__global__ void __launch_bounds__(128, 4)
k_edge(const float* __restrict__ r_ij, const int* __restrict__ nbrs,
       const float* __restrict__ Wr, const float* __restrict__ br,
       float* __restrict__ out)
{
    const int c = threadIdx.x;

    // Wr packed over rbf-index pairs: wp[k] = (Wr[2k], Wr[2k+1]) for this feature
    ull wp0[NRBF / 2], wp1[NRBF / 2], wp2[NRBF / 2];
#pragma unroll
    for (int k = 0; k < NRBF / 2; k++) {
        wp0[k] = f2pack(__ldg(&Wr[(2 * k) * 384 + c]),       __ldg(&Wr[(2 * k + 1) * 384 + c]));
        wp1[k] = f2pack(__ldg(&Wr[(2 * k) * 384 + 128 + c]), __ldg(&Wr[(2 * k + 1) * 384 + 128 + c]));
        wp2[k] = f2pack(__ldg(&Wr[(2 * k) * 384 + 256 + c]), __ldg(&Wr[(2 * k + 1) * 384 + 256 + c]));
    }
    const float br0 = __ldg(&br[c]), br1 = __ldg(&br[128 + c]), br2 = __ldg(&br[256 + c]);

    __shared__ __align__(16) float st[32][NRBF];   // t_n = sin(n x) * env / d
    __shared__ float senv[32], sux[32], suy[32], suz[32];
    __shared__ int sdst[32];

    for (int a = 0; a < APB; a++) {
        const int i = blockIdx.x * APB + a;
        const int deg = g_cnt[i], start = g_off[i];
        float accs = 0.f, avx = 0.f, avy = 0.f, avz = 0.f;

        for (int base = 0; base < deg; base += 32) {
            int m = min(32, deg - base);
            __syncthreads();
            if (c < m) {
                int e = g_eid[start + base + c];
                sdst[c] = nbrs[2 * e + 1];
                float rx = r_ij[3 * e], ry = r_ij[3 * e + 1], rz = r_ij[3 * e + 2];
                float d = sqrtf(fmaf(rx, rx, fmaf(ry, ry, rz * rz)));
                bool in = d < 5.0f;
                float invd = in ? __fdividef(1.f, d) : 0.f;
                float s1, c1;
                __sincosf(0.6283185307179586f * d, &s1, &c1);
                float env = in ? fmaf(0.5f, c1, 0.5f) : 0.f;
                float einv = env * invd;
                senv[c] = env;
                sux[c] = rx * invd; suy[c] = ry * invd; suz[c] = rz * invd;
                float c2 = 2.f * c1, sp = 0.f, sc = s1;
                st[c][0] = s1 * einv;
#pragma unroll
                for (int n = 1; n < NRBF; n++) {
                    float sn = fmaf(c2, sc, -sp);
                    sp = sc; sc = sn;
                    st[c][n] = sn * einv;
                }
            }
            __syncthreads();
            for (int j = 0; j < m; j++) {
                int dst = sdst[j];
                const float* ph = g_phi + (size_t)dst * 384;
                const float* vt = g_vt + (size_t)dst * 384;
                float ph0 = ph[c], ph1 = ph[c + 128], ph2 = ph[c + 256];
                float vx = vt[c], vy = vt[c + 128], vz = vt[c + 256];
                float env = senv[j], ux = sux[j], uy = suy[j], uz = suz[j];
                const ull* tp = (const ull*)&st[j][0];
                ull t = tp[0];
                ull w0p = f2mul(t, wp0[0]);
                ull w1p = f2mul(t, wp1[0]);
                ull w2p = f2mul(t, wp2[0]);
#pragma unroll
                for (int k = 1; k < NRBF / 2; k++) {
                    t = tp[k];
                    w0p = f2fma(t, wp0[k], w0p);
                    w1p = f2fma(t, wp1[k], w1p);
                    w2p = f2fma(t, wp2[k], w2p);
                }
                float l, h;
                f2unpack(w0p, l, h); float ws0 = fmaf(br0, env, l + h);
                f2unpack(w1p, l, h); float ws1 = fmaf(br1, env, l + h);
                f2unpack(w2p, l, h); float ws2 = fmaf(br2, env, l + h);
                float a0 = ph0 * ws0, a2 = ph2 * ws2;
                accs = fmaf(ph1, ws1, accs);
                avx = fmaf(a2, ux, fmaf(a0, vx, avx));
                avy = fmaf(a2, uy, fmaf(a0, vy, avy));
                avz = fmaf(a2, uz, fmaf(a0, vz, avz));
            }
        }
        size_t idx = (size_t)i * FEAT + c;
        out[idx] += accs;
        float* outv = out + (size_t)NATOMS * FEAT;
        outv[idx * 3 + 0] = avx;
        outv[idx * 3 + 1] = avy;
        outv[idx * 3 + 2] = avz;
    }
}

// ---------------- launch ----------------
extern "C" void kernel_launch(void* const* d_in, const int* in_sizes, int n_in,
                              void* d_out, int out_size)
{
    const float* s_j  = (const float*)d_in[0];
    const float* v_j  = (const float*)d_in[1];
    const float* r_ij = (const float*)d_in[2];
    const int*   nbrs = (const int*)  d_in[3];
    const float* W1 = (const float*)d_in[5];
    const float* b1 = (const float*)d_in[6];
    const float* W2 = (const float*)d_in[7];
    const float* b2 = (const float*)d_in[8];
    const float* Wr = (const float*)d_in[9];
    const float* br = (const float*)d_in[10];
    const float* Wd = (const float*)d_in[11];
    const float* bd = (const float*)d_in[12];
    float* out = (float*)d_out;

    float* g_h_p;   cudaGetSymbolAddress((void**)&g_h_p,   g_h);
    float* g_phi_p; cudaGetSymbolAddress((void**)&g_phi_p, g_phi);
    float* g_qkv_p; cudaGetSymbolAddress((void**)&g_qkv_p, g_qkv);

    cudaFuncSetAttribute(k_attn, cudaFuncAttributeMaxDynamicSharedMemorySize,
                         AT_SMEM * sizeof(float));

    k_zero<<<32, 256>>>();
    k_hist<<<NEDGES / 256, 256>>>(nbrs);
    k_scan<<<1, 1024>>>();
    k_scatter<<<NEDGES / 256, 256>>>(nbrs);
    k_vt<<<NATOMS, 128>>>(v_j);

    dim3 gh(2, 128);   // N=128
    k_gemm<<<gh, 256>>>(s_j, W1, b1, g_h_p, 128, 128, 1);
    dim3 gp(6, 128);   // N=384
    k_gemm<<<gp, 256>>>(g_h_p, W2, b2, g_phi_p, 128, 384, 0);
    k_gemm<<<gp, 256>>>(s_j, Wd, bd, g_qkv_p, 128, 384, 0);
    k_attn<<<NGRAPHS, 256, AT_SMEM * sizeof(float)>>>(g_qkv_p, out);
    k_edge<<<NATOMS / APB, 128>>>(r_ij, nbrs, Wr, br, out);
}